// round 15
// baseline (speedup 1.0000x reference)
#include <cuda_runtime.h>
#include <cuda_fp16.h>
#include <math.h>
#include <stdint.h>

#define FF 256   // frames (sequence length)
#define NN 400   // batch*joints (attention batch)
#define CC 128   // channels
#define HH 8     // heads
#define EE 16    // head dim
#define MM 128   // max relative pos
#define DD 257   // emb rows = 2*M+1

typedef unsigned long long u64;

// ---------- packed f32x2 helpers (Blackwell FFMA2 path; PTX-only) ----------
__device__ __forceinline__ u64 fma2_(u64 a, u64 b, u64 c) {
  u64 d; asm("fma.rn.f32x2 %0, %1, %2, %3;" : "=l"(d) : "l"(a), "l"(b), "l"(c)); return d;
}
__device__ __forceinline__ u64 add2_(u64 a, u64 b) {
  u64 d; asm("add.rn.f32x2 %0, %1, %2;" : "=l"(d) : "l"(a), "l"(b)); return d;
}
__device__ __forceinline__ u64 pack2_(float x, float y) {
  u64 d; asm("mov.b64 %0, {%1, %2};" : "=l"(d) : "f"(x), "f"(y)); return d;
}
__device__ __forceinline__ void unpack2_(u64 v, float& x, float& y) {
  asm("mov.b64 {%0, %1}, %2;" : "=f"(x), "=f"(y) : "l"(v));
}
__device__ __forceinline__ u64 h2_to_f2(__half2 h) {
  float2 f = __half22float2(h);
  return pack2_(f.x, f.y);
}
__device__ __forceinline__ void cpa8(unsigned d, const void* s) {
  asm volatile("cp.async.ca.shared.global [%0], [%1], 8;" :: "r"(d), "l"(s) : "memory");
}

// ---------------- scratch (device globals; no allocation allowed) ----------------
__device__ float g_tk[NN * CC];
__device__ float g_tv[NN * CC];
__device__ float g_Q[(size_t)NN * HH * FF * EE];
__device__ float g_K[(size_t)NN * HH * FF * EE];
__device__ float g_V[(size_t)NN * HH * FF * EE];
__device__ float g_Y[(size_t)FF * NN * CC];
__device__ float g_dummy[32];

// ---------------- kernel 0: tree_k / tree_v projections (tiny) ----------------
__global__ void __launch_bounds__(128) tree_proj_kernel(
    const float* __restrict__ te, const float* __restrict__ Wk,
    const float* __restrict__ Wv) {
  __shared__ float s[CC];
  int n = blockIdx.x, c = threadIdx.x;
  s[c] = te[n * CC + c];
  __syncthreads();
  float ak = 0.f, av = 0.f;
#pragma unroll 4
  for (int j = 0; j < CC; j++) {
    float t = s[j];
    ak += t * Wk[j * CC + c];
    av += t * Wv[j * CC + c];
  }
  g_tk[n * CC + c] = ak;
  g_tv[n * CC + c] = av;
}

// ---------------- kernel 1: QKV projection, cp.async double-buffered W ----------------
// grid (3200, 3): 32-row tiles of (F*N) x one of Q/K/V. block 256 (16x16 logical,
// 2 rows x 8 cols per thread). W streamed in 4 chunks of 32 c-columns, 2 buffers.
// ~70 live regs -> 3 CTAs/SM; W fetch hidden under chunk compute.
#define QWP 34  // W chunk pitch (34 mod 32 = 2 -> conflict-free 2-phase LDS.64)
__global__ void __launch_bounds__(256, 3) qkv_kernel(
    const float* __restrict__ x, const float* __restrict__ Wqkv) {
  extern __shared__ float sm[];
  float* sX = sm;                 // 32 x 128 = 4096
  float* sW0 = sX + 32 * 128;     // 128 x 34 = 4352
  float* sW1 = sW0 + 128 * QWP;   // 4352
  int m = blockIdx.y;
  int row0 = blockIdx.x * 32;
  int t = threadIdx.x;
  int tx = t & 15, ty = t >> 4;

  const float* Wc = Wqkv + (size_t)m * 128 * CC;
  unsigned sW0a = (unsigned)__cvta_generic_to_shared(sW0);
  unsigned sW1a = (unsigned)__cvta_generic_to_shared(sW1);

  // prefetch W chunk 0 and 1 (each: 128 rows x 16 8B-pairs)
#pragma unroll 1
  for (int kpre = 0; kpre < 2; kpre++) {
    unsigned ba = kpre ? sW1a : sW0a;
    for (int i = t; i < 2048; i += 256) {
      int r = i >> 4, p = i & 15;
      cpa8(ba + (unsigned)((r * QWP + p * 2) * 4), Wc + r * CC + kpre * 32 + p * 2);
    }
    asm volatile("cp.async.commit_group;" ::: "memory");
  }

  // load X tile (32 x 128)
  const float4* xsrc = (const float4*)(x + (size_t)row0 * CC);
  for (int i = t; i < 1024; i += 256) ((float4*)sX)[i] = xsrc[i];

  u64 acc2[2][8];
#pragma unroll
  for (int a = 0; a < 2; a++)
#pragma unroll
    for (int b = 0; b < 8; b++) acc2[a][b] = 0ull;

#pragma unroll 1
  for (int k = 0; k < 4; k++) {
    if (k == 3) asm volatile("cp.async.wait_group 0;" ::: "memory");
    else        asm volatile("cp.async.wait_group 1;" ::: "memory");
    __syncthreads();  // chunk k resident for all threads (also covers X on k=0)

    const float* buf = (k & 1) ? sW1 : sW0;
    int c0 = k * 32;
#pragma unroll
    for (int c = 0; c < 32; c += 2) {
      u64 xv[2], wv[8];
#pragma unroll
      for (int rr = 0; rr < 2; rr++)
        xv[rr] = *(const u64*)(sX + (ty * 2 + rr) * 128 + c0 + c);
#pragma unroll
      for (int oo = 0; oo < 8; oo++)
        wv[oo] = *(const u64*)(buf + (tx + oo * 16) * QWP + c);
#pragma unroll
      for (int rr = 0; rr < 2; rr++)
#pragma unroll
        for (int oo = 0; oo < 8; oo++) acc2[rr][oo] = fma2_(xv[rr], wv[oo], acc2[rr][oo]);
    }
    __syncthreads();  // done reading buffer before it is overwritten

    if (k + 2 < 4) {  // prefetch chunk k+2 into the buffer just freed
      unsigned ba = (k & 1) ? sW1a : sW0a;
      for (int i = t; i < 2048; i += 256) {
        int r = i >> 4, p = i & 15;
        cpa8(ba + (unsigned)((r * QWP + p * 2) * 4), Wc + r * CC + (k + 2) * 32 + p * 2);
      }
      asm volatile("cp.async.commit_group;" ::: "memory");
    }
  }

  float* dst = (m == 0) ? g_Q : (m == 1) ? g_K : g_V;
  const float* tadd = (m == 1) ? g_tk : (m == 2) ? g_tv : nullptr;
#pragma unroll
  for (int rr = 0; rr < 2; rr++) {
    int r = row0 + ty * 2 + rr;
    int f = r / NN, n = r - f * NN;
#pragma unroll
    for (int oo = 0; oo < 8; oo++) {
      int o = tx + oo * 16;
      float lo, hi;
      unpack2_(acc2[rr][oo], lo, hi);
      float v = lo + hi;
      if (tadd) v += tadd[n * CC + o];
      int h = o >> 4, e = o & 15;
      dst[(((size_t)(n * HH + h)) * FF + f) * EE + e] = v;
    }
  }
}

// ---------------- dummy kernel (fills ncu capture slots) ----------------
__global__ void dummy_kernel() {
  if (threadIdx.x < 32) g_dummy[threadIdx.x] = 0.f;
}

// ---------------- kernel 2: attention, one block per (n,h), online softmax ----------------
// R12-exact: grid (8 heads, 400 batch), block 256, thread t owns row l = t.
// Flash-style online softmax in chunks of 8; 3 CTAs/SM (measured 731 us, regs 80).
__global__ void __launch_bounds__(256, 3) attn_kernel(const float* __restrict__ emb) {
  extern __shared__ float sm[];
  float* sK = sm;                    // 256*16 = 4096
  float* sV = sK + 4096;             // 4096
  uint2* sEh = (uint2*)(sV + 4096);  // 4 planes * 257 entries * 8B (2056 floats)

  int h = blockIdx.x, n = blockIdx.y;
  int t = threadIdx.x;  // == l
  size_t boff = ((size_t)n * HH + h) * FF * EE;

  const float4* K4 = (const float4*)(g_K + boff);
  const float4* V4 = (const float4*)(g_V + boff);
  for (int i = t; i < 1024; i += 256) {
    ((float4*)sK)[i] = K4[i];
    ((float4*)sV)[i] = V4[i];
  }
  for (int i = t; i < DD * 4; i += 256) {
    int q = i / DD, d = i - q * DD;
    float4 v = *(const float4*)(emb + d * EE + q * 4);
    __half2 ha = __floats2half2_rn(v.x, v.y);
    __half2 hb = __floats2half2_rn(v.z, v.w);
    uint2 w;
    w.x = *(unsigned*)&ha;
    w.y = *(unsigned*)&hb;
    sEh[q * DD + d] = w;
  }

  u64 q2[8];
  {
    const float* qp = g_Q + boff + (size_t)t * EE;
#pragma unroll
    for (int p = 0; p < 8; p++) q2[p] = *(const u64*)(qp + 2 * p);
  }
  __syncthreads();

  const float scale = 0.25f;  // 1/sqrt(E)
  float m = -1e30f, sum = 0.f;
  u64 o2[8];
#pragma unroll
  for (int p = 0; p < 8; p++) o2[p] = 0ull;

#pragma unroll 1
  for (int c = 0; c < 32; c++) {  // 32 chunks of 8 s-values
    int s0 = c * 8;
    float S[8];
#pragma unroll
    for (int j = 0; j < 8; j++) {
      int s = s0 + j;
      int d = t - s;
      d = (d < -MM) ? -MM : (d > MM ? MM : d);
      d += MM;
      const float4* kr4 = (const float4*)(sK + s * 16);  // broadcast row: LDS.128 x4
      float4 ka = kr4[0], kb = kr4[1], kc = kr4[2], kd = kr4[3];
      u64 k2[8];
      k2[0] = *(u64*)&ka.x; k2[1] = *(u64*)&ka.z;
      k2[2] = *(u64*)&kb.x; k2[3] = *(u64*)&kb.z;
      k2[4] = *(u64*)&kc.x; k2[5] = *(u64*)&kc.z;
      k2[6] = *(u64*)&kd.x; k2[7] = *(u64*)&kd.z;
      const uint2* ed = sEh + d;
      u64 acc = 0ull;
#pragma unroll
      for (int q = 0; q < 4; q++) {
        uint2 w = ed[q * DD];  // per-lane contiguous LDS.64 (8B/lane)
        u64 e0 = h2_to_f2(*(__half2*)&w.x);
        u64 e1 = h2_to_f2(*(__half2*)&w.y);
        // q*k + q*pe + k*pe  =  q*(k+pe) + k*pe
        acc = fma2_(q2[2 * q], add2_(k2[2 * q], e0), acc);
        acc = fma2_(k2[2 * q], e0, acc);
        acc = fma2_(q2[2 * q + 1], add2_(k2[2 * q + 1], e1), acc);
        acc = fma2_(k2[2 * q + 1], e1, acc);
      }
      float lo, hi;
      unpack2_(acc, lo, hi);
      S[j] = lo + hi;
    }

    // online softmax update
    float cm = fmaxf(fmaxf(fmaxf(S[0], S[1]), fmaxf(S[2], S[3])),
                     fmaxf(fmaxf(S[4], S[5]), fmaxf(S[6], S[7])));
    float mn = fmaxf(m, cm);
    float corr = __expf((m - mn) * scale);
    sum *= corr;
    u64 corr2 = pack2_(corr, corr);
#pragma unroll
    for (int p = 0; p < 8; p++) o2[p] = fma2_(o2[p], corr2, 0ull);
#pragma unroll
    for (int j = 0; j < 8; j++) {
      float p = __expf((S[j] - mn) * scale);
      sum += p;
      u64 p2 = pack2_(p, p);
      const float4* vr4 = (const float4*)(sV + (s0 + j) * 16);
      float4 va = vr4[0], vb = vr4[1], vc = vr4[2], vd = vr4[3];
      o2[0] = fma2_(p2, *(u64*)&va.x, o2[0]);
      o2[1] = fma2_(p2, *(u64*)&va.z, o2[1]);
      o2[2] = fma2_(p2, *(u64*)&vb.x, o2[2]);
      o2[3] = fma2_(p2, *(u64*)&vb.z, o2[3]);
      o2[4] = fma2_(p2, *(u64*)&vc.x, o2[4]);
      o2[5] = fma2_(p2, *(u64*)&vc.z, o2[5]);
      o2[6] = fma2_(p2, *(u64*)&vd.x, o2[6]);
      o2[7] = fma2_(p2, *(u64*)&vd.z, o2[7]);
    }
    m = mn;
  }

  // normalize + write y[f=t][n][c]
  float inv = 1.f / sum;
  float4* dst4 = (float4*)(g_Y + ((size_t)t * NN + n) * CC + h * EE);
#pragma unroll
  for (int q = 0; q < 4; q++) {
    float a0, a1, b0, b1;
    unpack2_(o2[2 * q], a0, a1);
    unpack2_(o2[2 * q + 1], b0, b1);
    dst4[q] = make_float4(a0 * inv, a1 * inv, b0 * inv, b1 * inv);
  }
}

// ---------------- kernel 3: fused gate+AddNorm1 + FFN + residual + LN2 ----------------
// grid 1600 (64 rows each), block 256. Weights streamed via cp.async (8B chunks,
// 130-float pitch keeps only 8B alignment) OVERLAPPED with gate+LN1 phases.
#define WP 130
__global__ void __launch_bounds__(256) ffn_kernel(
    const float* __restrict__ x, const float* __restrict__ Wbeta,
    const float* __restrict__ g1, const float* __restrict__ bb1,
    const float* __restrict__ W1, const float* __restrict__ b1,
    const float* __restrict__ W2, const float* __restrict__ b2,
    const float* __restrict__ g2, const float* __restrict__ bb2,
    float* __restrict__ out) {
  extern __shared__ float sm[];
  float* sW1 = sm;                 // 128*130
  float* sW2 = sW1 + 128 * WP;     // 128*130
  float* sA = sW2 + 128 * WP;      // 64*130  (x -> u -> h1 -> ff+h1)
  float* sT = sA + 64 * WP;        // 64*130  (y -> gelu intermediate)
  float* sWb = sT + 64 * WP;       // 384
  float* sRed = sWb + 384;         // 256
  float* sMu = sRed + 256;         // 64 (gate, then mean)
  float* sRs = sMu + 64;           // 64

  int row0 = blockIdx.x * 64;
  int t = threadIdx.x;

  // ---- async weight prefetch: W1+W2 as 8B chunks (overlaps gate/LN1 below) ----
  {
    unsigned sW1a = (unsigned)__cvta_generic_to_shared(sW1);
    unsigned sW2a = (unsigned)__cvta_generic_to_shared(sW2);
    for (int i = t; i < 2 * 8192; i += 256) {
      int mIdx = i >> 13;          // 0: W1, 1: W2
      int j = i & 8191;            // 8B chunk within matrix
      int r = j >> 6, c2 = (j & 63) * 2;
      unsigned dst = (mIdx ? sW2a : sW1a) + (unsigned)((r * WP + c2) * 4);
      const float* src = (mIdx ? W2 : W1) + r * 128 + c2;
      cpa8(dst, src);
    }
    asm volatile("cp.async.commit_group;" ::: "memory");
  }

  for (int i = t; i < 64 * 128; i += 256) {
    int r = i >> 7, c = i & 127;
    size_t gi = (size_t)(row0 + r) * CC + c;
    sA[r * WP + c] = x[gi];
    sT[r * WP + c] = g_Y[gi];
  }
  for (int i = t; i < 384; i += 256) sWb[i] = Wbeta[i];
  __syncthreads();

  // ---- gate: z row-sum, sigmoid ----
  {
    int r = t >> 2, ch = t & 3;
    float ssum = 0.f;
#pragma unroll 8
    for (int i = 0; i < 32; i++) {
      int c = ch * 32 + i;
      float xv = sA[r * WP + c], yv = sT[r * WP + c];
      ssum += yv * sWb[c] + xv * sWb[CC + c] + (yv - xv) * sWb[2 * CC + c];
    }
    sRed[t] = ssum;
  }
  __syncthreads();
  if (t < 64) {
    float z = sRed[t * 4] + sRed[t * 4 + 1] + sRed[t * 4 + 2] + sRed[t * 4 + 3];
    sMu[t] = 1.f / (1.f + __expf(-z));  // gate per row
  }
  __syncthreads();
  // ---- u = g*x + (1-g)*y (overwrite sA) ----
  for (int i = t; i < 64 * 128; i += 256) {
    int r = i >> 7, c = i & 127;
    float gt = sMu[r];
    sA[r * WP + c] = gt * sA[r * WP + c] + (1.f - gt) * sT[r * WP + c];
  }
  __syncthreads();
  // ---- LayerNorm1 ----
  {
    int r = t >> 2, ch = t & 3;
    float s = 0.f;
#pragma unroll 8
    for (int i = 0; i < 32; i++) s += sA[r * WP + ch * 32 + i];
    sRed[t] = s;
  }
  __syncthreads();
  if (t < 64)
    sMu[t] = (sRed[t * 4] + sRed[t * 4 + 1] + sRed[t * 4 + 2] + sRed[t * 4 + 3]) * (1.f / CC);
  __syncthreads();
  {
    int r = t >> 2, ch = t & 3;
    float mu = sMu[r], s = 0.f;
#pragma unroll 8
    for (int i = 0; i < 32; i++) {
      float d = sA[r * WP + ch * 32 + i] - mu;
      s += d * d;
    }
    sRed[t] = s;
  }
  __syncthreads();
  if (t < 64) {
    float var = (sRed[t * 4] + sRed[t * 4 + 1] + sRed[t * 4 + 2] + sRed[t * 4 + 3]) * (1.f / CC);
    sRs[t] = rsqrtf(var + 1e-5f);
  }
  __syncthreads();
  for (int i = t; i < 64 * 128; i += 256) {
    int r = i >> 7, c = i & 127;
    sA[r * WP + c] = (sA[r * WP + c] - sMu[r]) * sRs[r] * g1[c] + bb1[c];
  }
  // weights must be resident before GEMM1
  asm volatile("cp.async.wait_group 0;" ::: "memory");
  __syncthreads();

  // ---- GEMM1 + GELU (packed f32x2 along c) ----
  int tx = t & 15, ty = t >> 4;
  u64 acc2[4][8];
#pragma unroll
  for (int a = 0; a < 4; a++)
#pragma unroll
    for (int b = 0; b < 8; b++) acc2[a][b] = 0ull;
#pragma unroll 4
  for (int c = 0; c < CC; c += 2) {
    u64 xv[4], wv[8];
#pragma unroll
    for (int rr = 0; rr < 4; rr++) xv[rr] = *(const u64*)(sA + (ty + rr * 16) * WP + c);
#pragma unroll
    for (int oo = 0; oo < 8; oo++) wv[oo] = *(const u64*)(sW1 + (tx + oo * 16) * WP + c);
#pragma unroll
    for (int rr = 0; rr < 4; rr++)
#pragma unroll
      for (int oo = 0; oo < 8; oo++) acc2[rr][oo] = fma2_(xv[rr], wv[oo], acc2[rr][oo]);
  }
  __syncthreads();  // sT (y) dead; about to overwrite
#pragma unroll
  for (int rr = 0; rr < 4; rr++) {
    int r = ty + rr * 16;
#pragma unroll
    for (int oo = 0; oo < 8; oo++) {
      int o = tx + oo * 16;
      float lo, hi;
      unpack2_(acc2[rr][oo], lo, hi);
      float v = lo + hi + b1[o];
      v = 0.5f * v * (1.f + erff(v * 0.70710678118654752f));  // exact GELU
      sT[r * WP + o] = v;
    }
  }
  __syncthreads();

  // ---- GEMM2 + residual ----
#pragma unroll
  for (int a = 0; a < 4; a++)
#pragma unroll
    for (int b = 0; b < 8; b++) acc2[a][b] = 0ull;
#pragma unroll 4
  for (int c = 0; c < CC; c += 2) {
    u64 xv[4], wv[8];
#pragma unroll
    for (int rr = 0; rr < 4; rr++) xv[rr] = *(const u64*)(sT + (ty + rr * 16) * WP + c);
#pragma unroll
    for (int oo = 0; oo < 8; oo++) wv[oo] = *(const u64*)(sW2 + (tx + oo * 16) * WP + c);
#pragma unroll
    for (int rr = 0; rr < 4; rr++)
#pragma unroll
      for (int oo = 0; oo < 8; oo++) acc2[rr][oo] = fma2_(xv[rr], wv[oo], acc2[rr][oo]);
  }
#pragma unroll
  for (int rr = 0; rr < 4; rr++) {
    int r = ty + rr * 16;
#pragma unroll
    for (int oo = 0; oo < 8; oo++) {
      int o = tx + oo * 16;
      float lo, hi;
      unpack2_(acc2[rr][oo], lo, hi);
      sA[r * WP + o] = lo + hi + b2[o] + sA[r * WP + o];  // ff + h1 (owner slot)
    }
  }
  __syncthreads();

  // ---- LayerNorm2 + store ----
  {
    int r = t >> 2, ch = t & 3;
    float s = 0.f;
#pragma unroll 8
    for (int i = 0; i < 32; i++) s += sA[r * WP + ch * 32 + i];
    sRed[t] = s;
  }
  __syncthreads();
  if (t < 64)
    sMu[t] = (sRed[t * 4] + sRed[t * 4 + 1] + sRed[t * 4 + 2] + sRed[t * 4 + 3]) * (1.f / CC);
  __syncthreads();
  {
    int r = t >> 2, ch = t & 3;
    float mu = sMu[r], s = 0.f;
#pragma unroll 8
    for (int i = 0; i < 32; i++) {
      float d = sA[r * WP + ch * 32 + i] - mu;
      s += d * d;
    }
    sRed[t] = s;
  }
  __syncthreads();
  if (t < 64) {
    float var = (sRed[t * 4] + sRed[t * 4 + 1] + sRed[t * 4 + 2] + sRed[t * 4 + 3]) * (1.f / CC);
    sRs[t] = rsqrtf(var + 1e-5f);
  }
  __syncthreads();
  for (int i = t; i < 64 * 128; i += 256) {
    int r = i >> 7, c = i & 127;
    float v = (sA[r * WP + c] - sMu[r]) * sRs[r] * g2[c] + bb2[c];
    out[(size_t)(row0 + r) * CC + c] = v;
  }
}

// ---------------- launch ----------------
extern "C" void kernel_launch(void* const* d_in, const int* in_sizes, int n_in,
                              void* d_out, int out_size) {
  const float* x    = (const float*)d_in[0];
  const float* te   = (const float*)d_in[1];
  const float* Wqkv = (const float*)d_in[2];
  const float* Wtk  = (const float*)d_in[3];
  const float* Wtv  = (const float*)d_in[4];
  const float* emb  = (const float*)d_in[5];
  const float* Wb   = (const float*)d_in[6];
  const float* ln1g = (const float*)d_in[7];
  const float* ln1b = (const float*)d_in[8];
  const float* ln2g = (const float*)d_in[9];
  const float* ln2b = (const float*)d_in[10];
  const float* W1   = (const float*)d_in[11];
  const float* b1   = (const float*)d_in[12];
  const float* W2   = (const float*)d_in[13];
  const float* b2   = (const float*)d_in[14];
  float* out = (float*)d_out;

  const int smem_qkv = (32 * 128 + 2 * 128 * QWP) * 4;                         // 51200
  const int smem_att = (4096 + 4096 + 2056) * 4;                               // 40992
  const int smem_ffn = (2 * 128 * WP + 2 * 64 * WP + 384 + 256 + 64 + 64) * 4; // 202752

  cudaFuncSetAttribute(qkv_kernel, cudaFuncAttributeMaxDynamicSharedMemorySize, smem_qkv);
  cudaFuncSetAttribute(attn_kernel, cudaFuncAttributeMaxDynamicSharedMemorySize, smem_att);
  cudaFuncSetAttribute(ffn_kernel, cudaFuncAttributeMaxDynamicSharedMemorySize, smem_ffn);

  // ncu profiles the 4th launch -> qkv (to verify this round's change)
  tree_proj_kernel<<<NN, 128>>>(te, Wtk, Wtv);
  dummy_kernel<<<1, 32>>>();
  dummy_kernel<<<1, 32>>>();
  qkv_kernel<<<dim3(FF * NN / 32, 3), 256, smem_qkv>>>(x, Wqkv);
  attn_kernel<<<dim3(HH, NN), 256, smem_att>>>(emb);
  ffn_kernel<<<FF * NN / 64, 256, smem_ffn>>>(x, Wb, ln1g, ln1b, W1, b1, W2, b2,
                                              ln2g, ln2b, out);
}

// round 16
// speedup vs baseline: 1.0277x; 1.0277x over previous
#include <cuda_runtime.h>
#include <cuda_fp16.h>
#include <math.h>
#include <stdint.h>

#define FF 256   // frames (sequence length)
#define NN 400   // batch*joints (attention batch)
#define CC 128   // channels
#define HH 8     // heads
#define EE 16    // head dim
#define MM 128   // max relative pos
#define DD 257   // emb rows = 2*M+1

typedef unsigned long long u64;

// ---------- packed f32x2 helpers (Blackwell FFMA2 path; PTX-only) ----------
__device__ __forceinline__ u64 fma2_(u64 a, u64 b, u64 c) {
  u64 d; asm("fma.rn.f32x2 %0, %1, %2, %3;" : "=l"(d) : "l"(a), "l"(b), "l"(c)); return d;
}
__device__ __forceinline__ u64 add2_(u64 a, u64 b) {
  u64 d; asm("add.rn.f32x2 %0, %1, %2;" : "=l"(d) : "l"(a), "l"(b)); return d;
}
__device__ __forceinline__ u64 pack2_(float x, float y) {
  u64 d; asm("mov.b64 %0, {%1, %2};" : "=l"(d) : "f"(x), "f"(y)); return d;
}
__device__ __forceinline__ void unpack2_(u64 v, float& x, float& y) {
  asm("mov.b64 {%0, %1}, %2;" : "=f"(x), "=f"(y) : "l"(v));
}
__device__ __forceinline__ u64 h2_to_f2(__half2 h) {
  float2 f = __half22float2(h);
  return pack2_(f.x, f.y);
}
__device__ __forceinline__ void cpa8(unsigned d, const void* s) {
  asm volatile("cp.async.ca.shared.global [%0], [%1], 8;" :: "r"(d), "l"(s) : "memory");
}

// ---------------- scratch (device globals; no allocation allowed) ----------------
__device__ float g_tk[NN * CC];
__device__ float g_tv[NN * CC];
__device__ float g_Q[(size_t)NN * HH * FF * EE];
__device__ float g_K[(size_t)NN * HH * FF * EE];
__device__ float g_V[(size_t)NN * HH * FF * EE];
__device__ float g_Y[(size_t)FF * NN * CC];
__device__ float g_dummy[32];

// ---------------- kernel 0: tree_k / tree_v projections (tiny) ----------------
__global__ void __launch_bounds__(128) tree_proj_kernel(
    const float* __restrict__ te, const float* __restrict__ Wk,
    const float* __restrict__ Wv) {
  __shared__ float s[CC];
  int n = blockIdx.x, c = threadIdx.x;
  s[c] = te[n * CC + c];
  __syncthreads();
  float ak = 0.f, av = 0.f;
#pragma unroll 4
  for (int j = 0; j < CC; j++) {
    float t = s[j];
    ak += t * Wk[j * CC + c];
    av += t * Wv[j * CC + c];
  }
  g_tk[n * CC + c] = ak;
  g_tv[n * CC + c] = av;
}

// ---------------- kernel 1: QKV projection (R14-exact: monolithic, 64-row tiles) ----------------
#define WP 130
__global__ void __launch_bounds__(256, 2) qkv_kernel(
    const float* __restrict__ x, const float* __restrict__ Wqkv) {
  extern __shared__ float sm[];
  float* sW = sm;             // 128 x 130
  float* sX = sm + 128 * WP;  // 64 x 128
  int m = blockIdx.y;
  int row0 = blockIdx.x * 64;
  int t = threadIdx.x;

  const float* Wc = Wqkv + (size_t)m * 128 * CC;
  for (int i = t; i < 128 * CC; i += 256) {
    int r = i >> 7, c = i & 127;
    sW[r * WP + c] = Wc[i];
  }
  const float4* xsrc = (const float4*)(x + (size_t)row0 * CC);
  for (int i = t; i < 64 * CC / 4; i += 256) ((float4*)sX)[i] = xsrc[i];
  __syncthreads();

  int tx = t & 15, ty = t >> 4;
  u64 acc2[4][8];
#pragma unroll
  for (int a = 0; a < 4; a++)
#pragma unroll
    for (int b = 0; b < 8; b++) acc2[a][b] = 0ull;

#pragma unroll 4
  for (int c = 0; c < CC; c += 2) {
    u64 xv[4], wv[8];
#pragma unroll
    for (int rr = 0; rr < 4; rr++) xv[rr] = *(const u64*)(sX + (ty + rr * 16) * CC + c);
#pragma unroll
    for (int oo = 0; oo < 8; oo++) wv[oo] = *(const u64*)(sW + (tx + oo * 16) * WP + c);
#pragma unroll
    for (int rr = 0; rr < 4; rr++)
#pragma unroll
      for (int oo = 0; oo < 8; oo++) acc2[rr][oo] = fma2_(xv[rr], wv[oo], acc2[rr][oo]);
  }

  float* dst = (m == 0) ? g_Q : (m == 1) ? g_K : g_V;
  const float* tadd = (m == 1) ? g_tk : (m == 2) ? g_tv : nullptr;
#pragma unroll
  for (int rr = 0; rr < 4; rr++) {
    int r = row0 + ty + rr * 16;
    int f = r / NN, n = r - f * NN;
#pragma unroll
    for (int oo = 0; oo < 8; oo++) {
      int o = tx + oo * 16;
      float lo, hi;
      unpack2_(acc2[rr][oo], lo, hi);
      float v = lo + hi;
      if (tadd) v += tadd[n * CC + o];
      int h = o >> 4, e = o & 15;
      dst[(((size_t)(n * HH + h)) * FF + f) * EE + e] = v;
    }
  }
}

// ---------------- dummy kernel (fills ncu capture slots) ----------------
__global__ void dummy_kernel() {
  if (threadIdx.x < 32) g_dummy[threadIdx.x] = 0.f;
}

// ---------------- kernel 2: attention, one block per (n,h), online softmax ----------------
// R12 structure (grid (8,400), block 256, thread t owns row l=t, 3 CTAs/SM).
// Tweak: scale*log2(e) folded into S at creation; softmax runs in the scaled
// domain with exp2f -> one fewer fma-pipe op per s in the exp path.
__global__ void __launch_bounds__(256, 3) attn_kernel(const float* __restrict__ emb) {
  extern __shared__ float sm[];
  float* sK = sm;                    // 256*16 = 4096
  float* sV = sK + 4096;             // 4096
  uint2* sEh = (uint2*)(sV + 4096);  // 4 planes * 257 entries * 8B (2056 floats)

  int h = blockIdx.x, n = blockIdx.y;
  int t = threadIdx.x;  // == l
  size_t boff = ((size_t)n * HH + h) * FF * EE;

  const float4* K4 = (const float4*)(g_K + boff);
  const float4* V4 = (const float4*)(g_V + boff);
  for (int i = t; i < 1024; i += 256) {
    ((float4*)sK)[i] = K4[i];
    ((float4*)sV)[i] = V4[i];
  }
  for (int i = t; i < DD * 4; i += 256) {
    int q = i / DD, d = i - q * DD;
    float4 v = *(const float4*)(emb + d * EE + q * 4);
    __half2 ha = __floats2half2_rn(v.x, v.y);
    __half2 hb = __floats2half2_rn(v.z, v.w);
    uint2 w;
    w.x = *(unsigned*)&ha;
    w.y = *(unsigned*)&hb;
    sEh[q * DD + d] = w;
  }

  u64 q2[8];
  {
    const float* qp = g_Q + boff + (size_t)t * EE;
#pragma unroll
    for (int p = 0; p < 8; p++) q2[p] = *(const u64*)(qp + 2 * p);
  }
  __syncthreads();

  const float lscale = 0.25f * 1.4426950408889634f;  // log2(e)/sqrt(E)
  float m = -1e30f, sum = 0.f;
  u64 o2[8];
#pragma unroll
  for (int p = 0; p < 8; p++) o2[p] = 0ull;

#pragma unroll 1
  for (int c = 0; c < 32; c++) {  // 32 chunks of 8 s-values
    int s0 = c * 8;
    float S[8];
#pragma unroll
    for (int j = 0; j < 8; j++) {
      int s = s0 + j;
      int d = t - s;
      d = (d < -MM) ? -MM : (d > MM ? MM : d);
      d += MM;
      const float4* kr4 = (const float4*)(sK + s * 16);  // broadcast row: LDS.128 x4
      float4 ka = kr4[0], kb = kr4[1], kc = kr4[2], kd = kr4[3];
      u64 k2[8];
      k2[0] = *(u64*)&ka.x; k2[1] = *(u64*)&ka.z;
      k2[2] = *(u64*)&kb.x; k2[3] = *(u64*)&kb.z;
      k2[4] = *(u64*)&kc.x; k2[5] = *(u64*)&kc.z;
      k2[6] = *(u64*)&kd.x; k2[7] = *(u64*)&kd.z;
      const uint2* ed = sEh + d;
      u64 acc = 0ull;
#pragma unroll
      for (int q = 0; q < 4; q++) {
        uint2 w = ed[q * DD];  // per-lane contiguous LDS.64 (8B/lane)
        u64 e0 = h2_to_f2(*(__half2*)&w.x);
        u64 e1 = h2_to_f2(*(__half2*)&w.y);
        // q*k + q*pe + k*pe  =  q*(k+pe) + k*pe
        acc = fma2_(q2[2 * q], add2_(k2[2 * q], e0), acc);
        acc = fma2_(k2[2 * q], e0, acc);
        acc = fma2_(q2[2 * q + 1], add2_(k2[2 * q + 1], e1), acc);
        acc = fma2_(k2[2 * q + 1], e1, acc);
      }
      float lo, hi;
      unpack2_(acc, lo, hi);
      S[j] = (lo + hi) * lscale;  // scaled domain: exp(x*scale) == 2^S
    }

    // online softmax update (scaled domain, exp2)
    float cm = fmaxf(fmaxf(fmaxf(S[0], S[1]), fmaxf(S[2], S[3])),
                     fmaxf(fmaxf(S[4], S[5]), fmaxf(S[6], S[7])));
    float mn = fmaxf(m, cm);
    float corr = exp2f(m - mn);
    sum *= corr;
    u64 corr2 = pack2_(corr, corr);
#pragma unroll
    for (int p = 0; p < 8; p++) o2[p] = fma2_(o2[p], corr2, 0ull);
#pragma unroll
    for (int j = 0; j < 8; j++) {
      float p = exp2f(S[j] - mn);
      sum += p;
      u64 p2 = pack2_(p, p);
      const float4* vr4 = (const float4*)(sV + (s0 + j) * 16);
      float4 va = vr4[0], vb = vr4[1], vc = vr4[2], vd = vr4[3];
      o2[0] = fma2_(p2, *(u64*)&va.x, o2[0]);
      o2[1] = fma2_(p2, *(u64*)&va.z, o2[1]);
      o2[2] = fma2_(p2, *(u64*)&vb.x, o2[2]);
      o2[3] = fma2_(p2, *(u64*)&vb.z, o2[3]);
      o2[4] = fma2_(p2, *(u64*)&vc.x, o2[4]);
      o2[5] = fma2_(p2, *(u64*)&vc.z, o2[5]);
      o2[6] = fma2_(p2, *(u64*)&vd.x, o2[6]);
      o2[7] = fma2_(p2, *(u64*)&vd.z, o2[7]);
    }
    m = mn;
  }

  // normalize + write y[f=t][n][c]
  float inv = 1.f / sum;
  float4* dst4 = (float4*)(g_Y + ((size_t)t * NN + n) * CC + h * EE);
#pragma unroll
  for (int q = 0; q < 4; q++) {
    float a0, a1, b0, b1;
    unpack2_(o2[2 * q], a0, a1);
    unpack2_(o2[2 * q + 1], b0, b1);
    dst4[q] = make_float4(a0 * inv, a1 * inv, b0 * inv, b1 * inv);
  }
}

// ---------------- kernel 3: fused gate+AddNorm1 + FFN + residual + LN2 ----------------
// grid 1600 (64 rows each), block 256. Weights streamed via cp.async (8B chunks)
// OVERLAPPED with gate+LN1 phases. (R14-exact.)
__global__ void __launch_bounds__(256) ffn_kernel(
    const float* __restrict__ x, const float* __restrict__ Wbeta,
    const float* __restrict__ g1, const float* __restrict__ bb1,
    const float* __restrict__ W1, const float* __restrict__ b1,
    const float* __restrict__ W2, const float* __restrict__ b2,
    const float* __restrict__ g2, const float* __restrict__ bb2,
    float* __restrict__ out) {
  extern __shared__ float sm[];
  float* sW1 = sm;                 // 128*130
  float* sW2 = sW1 + 128 * WP;     // 128*130
  float* sA = sW2 + 128 * WP;      // 64*130  (x -> u -> h1 -> ff+h1)
  float* sT = sA + 64 * WP;        // 64*130  (y -> gelu intermediate)
  float* sWb = sT + 64 * WP;       // 384
  float* sRed = sWb + 384;         // 256
  float* sMu = sRed + 256;         // 64 (gate, then mean)
  float* sRs = sMu + 64;           // 64

  int row0 = blockIdx.x * 64;
  int t = threadIdx.x;

  // ---- async weight prefetch: W1+W2 as 8B chunks (overlaps gate/LN1 below) ----
  {
    unsigned sW1a = (unsigned)__cvta_generic_to_shared(sW1);
    unsigned sW2a = (unsigned)__cvta_generic_to_shared(sW2);
    for (int i = t; i < 2 * 8192; i += 256) {
      int mIdx = i >> 13;
      int j = i & 8191;
      int r = j >> 6, c2 = (j & 63) * 2;
      unsigned dst = (mIdx ? sW2a : sW1a) + (unsigned)((r * WP + c2) * 4);
      const float* src = (mIdx ? W2 : W1) + r * 128 + c2;
      cpa8(dst, src);
    }
    asm volatile("cp.async.commit_group;" ::: "memory");
  }

  for (int i = t; i < 64 * 128; i += 256) {
    int r = i >> 7, c = i & 127;
    size_t gi = (size_t)(row0 + r) * CC + c;
    sA[r * WP + c] = x[gi];
    sT[r * WP + c] = g_Y[gi];
  }
  for (int i = t; i < 384; i += 256) sWb[i] = Wbeta[i];
  __syncthreads();

  // ---- gate: z row-sum, sigmoid ----
  {
    int r = t >> 2, ch = t & 3;
    float ssum = 0.f;
#pragma unroll 8
    for (int i = 0; i < 32; i++) {
      int c = ch * 32 + i;
      float xv = sA[r * WP + c], yv = sT[r * WP + c];
      ssum += yv * sWb[c] + xv * sWb[CC + c] + (yv - xv) * sWb[2 * CC + c];
    }
    sRed[t] = ssum;
  }
  __syncthreads();
  if (t < 64) {
    float z = sRed[t * 4] + sRed[t * 4 + 1] + sRed[t * 4 + 2] + sRed[t * 4 + 3];
    sMu[t] = 1.f / (1.f + __expf(-z));  // gate per row
  }
  __syncthreads();
  for (int i = t; i < 64 * 128; i += 256) {
    int r = i >> 7, c = i & 127;
    float gt = sMu[r];
    sA[r * WP + c] = gt * sA[r * WP + c] + (1.f - gt) * sT[r * WP + c];
  }
  __syncthreads();
  // ---- LayerNorm1 ----
  {
    int r = t >> 2, ch = t & 3;
    float s = 0.f;
#pragma unroll 8
    for (int i = 0; i < 32; i++) s += sA[r * WP + ch * 32 + i];
    sRed[t] = s;
  }
  __syncthreads();
  if (t < 64)
    sMu[t] = (sRed[t * 4] + sRed[t * 4 + 1] + sRed[t * 4 + 2] + sRed[t * 4 + 3]) * (1.f / CC);
  __syncthreads();
  {
    int r = t >> 2, ch = t & 3;
    float mu = sMu[r], s = 0.f;
#pragma unroll 8
    for (int i = 0; i < 32; i++) {
      float d = sA[r * WP + ch * 32 + i] - mu;
      s += d * d;
    }
    sRed[t] = s;
  }
  __syncthreads();
  if (t < 64) {
    float var = (sRed[t * 4] + sRed[t * 4 + 1] + sRed[t * 4 + 2] + sRed[t * 4 + 3]) * (1.f / CC);
    sRs[t] = rsqrtf(var + 1e-5f);
  }
  __syncthreads();
  for (int i = t; i < 64 * 128; i += 256) {
    int r = i >> 7, c = i & 127;
    sA[r * WP + c] = (sA[r * WP + c] - sMu[r]) * sRs[r] * g1[c] + bb1[c];
  }
  asm volatile("cp.async.wait_group 0;" ::: "memory");
  __syncthreads();

  // ---- GEMM1 + GELU (packed f32x2 along c) ----
  int tx = t & 15, ty = t >> 4;
  u64 acc2[4][8];
#pragma unroll
  for (int a = 0; a < 4; a++)
#pragma unroll
    for (int b = 0; b < 8; b++) acc2[a][b] = 0ull;
#pragma unroll 4
  for (int c = 0; c < CC; c += 2) {
    u64 xv[4], wv[8];
#pragma unroll
    for (int rr = 0; rr < 4; rr++) xv[rr] = *(const u64*)(sA + (ty + rr * 16) * WP + c);
#pragma unroll
    for (int oo = 0; oo < 8; oo++) wv[oo] = *(const u64*)(sW1 + (tx + oo * 16) * WP + c);
#pragma unroll
    for (int rr = 0; rr < 4; rr++)
#pragma unroll
      for (int oo = 0; oo < 8; oo++) acc2[rr][oo] = fma2_(xv[rr], wv[oo], acc2[rr][oo]);
  }
  __syncthreads();
#pragma unroll
  for (int rr = 0; rr < 4; rr++) {
    int r = ty + rr * 16;
#pragma unroll
    for (int oo = 0; oo < 8; oo++) {
      int o = tx + oo * 16;
      float lo, hi;
      unpack2_(acc2[rr][oo], lo, hi);
      float v = lo + hi + b1[o];
      v = 0.5f * v * (1.f + erff(v * 0.70710678118654752f));  // exact GELU
      sT[r * WP + o] = v;
    }
  }
  __syncthreads();

  // ---- GEMM2 + residual ----
#pragma unroll
  for (int a = 0; a < 4; a++)
#pragma unroll
    for (int b = 0; b < 8; b++) acc2[a][b] = 0ull;
#pragma unroll 4
  for (int c = 0; c < CC; c += 2) {
    u64 xv[4], wv[8];
#pragma unroll
    for (int rr = 0; rr < 4; rr++) xv[rr] = *(const u64*)(sT + (ty + rr * 16) * WP + c);
#pragma unroll
    for (int oo = 0; oo < 8; oo++) wv[oo] = *(const u64*)(sW2 + (tx + oo * 16) * WP + c);
#pragma unroll
    for (int rr = 0; rr < 4; rr++)
#pragma unroll
      for (int oo = 0; oo < 8; oo++) acc2[rr][oo] = fma2_(xv[rr], wv[oo], acc2[rr][oo]);
  }
#pragma unroll
  for (int rr = 0; rr < 4; rr++) {
    int r = ty + rr * 16;
#pragma unroll
    for (int oo = 0; oo < 8; oo++) {
      int o = tx + oo * 16;
      float lo, hi;
      unpack2_(acc2[rr][oo], lo, hi);
      sA[r * WP + o] = lo + hi + b2[o] + sA[r * WP + o];  // ff + h1 (owner slot)
    }
  }
  __syncthreads();

  // ---- LayerNorm2 + store ----
  {
    int r = t >> 2, ch = t & 3;
    float s = 0.f;
#pragma unroll 8
    for (int i = 0; i < 32; i++) s += sA[r * WP + ch * 32 + i];
    sRed[t] = s;
  }
  __syncthreads();
  if (t < 64)
    sMu[t] = (sRed[t * 4] + sRed[t * 4 + 1] + sRed[t * 4 + 2] + sRed[t * 4 + 3]) * (1.f / CC);
  __syncthreads();
  {
    int r = t >> 2, ch = t & 3;
    float mu = sMu[r], s = 0.f;
#pragma unroll 8
    for (int i = 0; i < 32; i++) {
      float d = sA[r * WP + ch * 32 + i] - mu;
      s += d * d;
    }
    sRed[t] = s;
  }
  __syncthreads();
  if (t < 64) {
    float var = (sRed[t * 4] + sRed[t * 4 + 1] + sRed[t * 4 + 2] + sRed[t * 4 + 3]) * (1.f / CC);
    sRs[t] = rsqrtf(var + 1e-5f);
  }
  __syncthreads();
  for (int i = t; i < 64 * 128; i += 256) {
    int r = i >> 7, c = i & 127;
    float v = (sA[r * WP + c] - sMu[r]) * sRs[r] * g2[c] + bb2[c];
    out[(size_t)(row0 + r) * CC + c] = v;
  }
}

// ---------------- launch ----------------
extern "C" void kernel_launch(void* const* d_in, const int* in_sizes, int n_in,
                              void* d_out, int out_size) {
  const float* x    = (const float*)d_in[0];
  const float* te   = (const float*)d_in[1];
  const float* Wqkv = (const float*)d_in[2];
  const float* Wtk  = (const float*)d_in[3];
  const float* Wtv  = (const float*)d_in[4];
  const float* emb  = (const float*)d_in[5];
  const float* Wb   = (const float*)d_in[6];
  const float* ln1g = (const float*)d_in[7];
  const float* ln1b = (const float*)d_in[8];
  const float* ln2g = (const float*)d_in[9];
  const float* ln2b = (const float*)d_in[10];
  const float* W1   = (const float*)d_in[11];
  const float* b1   = (const float*)d_in[12];
  const float* W2   = (const float*)d_in[13];
  const float* b2   = (const float*)d_in[14];
  float* out = (float*)d_out;

  const int smem_qkv = (128 * WP + 64 * CC) * 4;                               // 99328
  const int smem_att = (4096 + 4096 + 2056) * 4;                               // 40992
  const int smem_ffn = (2 * 128 * WP + 2 * 64 * WP + 384 + 256 + 64 + 64) * 4; // 202752

  cudaFuncSetAttribute(qkv_kernel, cudaFuncAttributeMaxDynamicSharedMemorySize, smem_qkv);
  cudaFuncSetAttribute(attn_kernel, cudaFuncAttributeMaxDynamicSharedMemorySize, smem_att);
  cudaFuncSetAttribute(ffn_kernel, cudaFuncAttributeMaxDynamicSharedMemorySize, smem_ffn);

  // ncu profiles the 4th launch -> attn (to verify the exp2 fold)
  tree_proj_kernel<<<NN, 128>>>(te, Wtk, Wtv);
  dummy_kernel<<<1, 32>>>();
  qkv_kernel<<<dim3(FF * NN / 64, 3), 256, smem_qkv>>>(x, Wqkv);
  attn_kernel<<<dim3(HH, NN), 256, smem_att>>>(emb);
  ffn_kernel<<<FF * NN / 64, 256, smem_ffn>>>(x, Wb, ln1g, ln1b, W1, b1, W2, b2,
                                              ln2g, ln2b, out);
}